// round 8
// baseline (speedup 1.0000x reference)
#include <cuda_runtime.h>

// Scratch: split-K partials [16][512*256] (8 MB) and x3 [512 x 64].
static __device__ float g_part[16][512 * 256];
static __device__ float g_x3[512 * 64];

// ---------------------------------------------------------------------------
// Kernel A1: split-K partial GEMM.  part[z] = x[32r x 32k] @ w2^T[32k x 64h]
// grid (16 rowTiles, 4 hidTiles, 16 kSplits) = 1024 blocks, 128 threads.
// regs ~72 -> 7 blocks/SM -> all 1024 blocks resident, ~28 warps/SM.
// 4x4 register tiles, rows strided 8, cols strided 16 (conflict-free LDS.128).
// ---------------------------------------------------------------------------
__global__ void __launch_bounds__(128) gemm1_part_kernel(
    const float* __restrict__ x,    // [512, 512]
    const float* __restrict__ w2)   // [256, 512]
{
    __shared__ float xs[32][36];
    __shared__ float ws[64][36];

    const int t  = threadIdx.x;
    const int r0 = blockIdx.x * 32;
    const int h0 = blockIdx.y * 64;
    const int k0 = blockIdx.z * 32;

    // load x tile: 32 rows x 32 k = 256 float4 (2 per thread), coalesced
    #pragma unroll
    for (int i = 0; i < 2; ++i) {
        const int idx = t + i * 128;
        const int r   = idx >> 3;          // 0..31
        const int kq  = (idx & 7) * 4;     // 0..28
        float4 v = *reinterpret_cast<const float4*>(
            x + (size_t)(r0 + r) * 512 + k0 + kq);
        *reinterpret_cast<float4*>(&xs[r][kq]) = v;
    }
    // load w2 tile: 64 rows x 32 k = 512 float4 (4 per thread), coalesced
    #pragma unroll
    for (int i = 0; i < 4; ++i) {
        const int idx = t + i * 128;
        const int r   = idx >> 3;          // 0..63
        const int kq  = (idx & 7) * 4;
        float4 v = *reinterpret_cast<const float4*>(
            w2 + (size_t)(h0 + r) * 512 + k0 + kq);
        *reinterpret_cast<float4*>(&ws[r][kq]) = v;
    }

    float acc[4][4];
    #pragma unroll
    for (int i = 0; i < 4; ++i)
        #pragma unroll
        for (int j = 0; j < 4; ++j) acc[i][j] = 0.f;

    const int tx = t & 15;   // cols tx, tx+16, tx+32, tx+48
    const int ty = t >> 4;   // rows ty, ty+8, ty+16, ty+24

    __syncthreads();

    #pragma unroll
    for (int kq = 0; kq < 32; kq += 4) {
        float4 a[4], bv[4];
        #pragma unroll
        for (int i = 0; i < 4; ++i)
            a[i] = *reinterpret_cast<const float4*>(&xs[ty + 8 * i][kq]);
        #pragma unroll
        for (int j = 0; j < 4; ++j)
            bv[j] = *reinterpret_cast<const float4*>(&ws[tx + 16 * j][kq]);
        #pragma unroll
        for (int i = 0; i < 4; ++i)
            #pragma unroll
            for (int j = 0; j < 4; ++j) {
                acc[i][j] = fmaf(a[i].x, bv[j].x, acc[i][j]);
                acc[i][j] = fmaf(a[i].y, bv[j].y, acc[i][j]);
                acc[i][j] = fmaf(a[i].z, bv[j].z, acc[i][j]);
                acc[i][j] = fmaf(a[i].w, bv[j].w, acc[i][j]);
            }
    }

    float* dst = g_part[blockIdx.z];
    #pragma unroll
    for (int i = 0; i < 4; ++i)
        #pragma unroll
        for (int j = 0; j < 4; ++j)
            dst[(size_t)(r0 + ty + 8 * i) * 256 + h0 + tx + 16 * j] = acc[i][j];
}

// ---------------------------------------------------------------------------
// Kernel A2: reduce 16 partials + bias + LeakyReLU, GEMM2 with w3 staged
// through smem, + softmaxes -> x3.  8 rows/block, 256 threads, grid 64.
// ---------------------------------------------------------------------------
__global__ void __launch_bounds__(256) head_kernel(
    const float* __restrict__ b2,   // [256]
    const float* __restrict__ w3,   // [55, 256]
    const float* __restrict__ b3)   // [55]
{
    __shared__ float hs[8][260];
    __shared__ float ws[55][68];
    __shared__ float zs[8][60];

    const int t  = threadIdx.x;
    const int r0 = blockIdx.x * 8;

    const float bb = b2[t];
    #pragma unroll
    for (int i = 0; i < 8; ++i) {
        const size_t off = (size_t)(r0 + i) * 256 + t;
        float s = bb;
        #pragma unroll
        for (int z = 0; z < 16; ++z) s += g_part[z][off];
        hs[i][t] = (s >= 0.f) ? s : 0.01f * s;
    }

    const int o0 = t;
    const int o1 = t + 256;
    const int r0o = o0 & 7, c0o = o0 >> 3;
    const int r1o = o1 & 7, c1o = o1 >> 3;
    float acc0 = 0.f, acc1 = 0.f;

    #pragma unroll
    for (int chunk = 0; chunk < 4; ++chunk) {
        __syncthreads();
        for (int idx = t; idx < 880; idx += 256) {
            const int c = idx >> 4;
            const int j = (idx & 15) * 4;
            float4 v = *reinterpret_cast<const float4*>(
                w3 + (size_t)c * 256 + chunk * 64 + j);
            *reinterpret_cast<float4*>(&ws[c][j]) = v;
        }
        __syncthreads();

        #pragma unroll 4
        for (int k = 0; k < 16; ++k) {
            const int kj = k * 4;
            {
                const float4 a = *reinterpret_cast<const float4*>(
                    &hs[r0o][chunk * 64 + kj]);
                const float4 w = *reinterpret_cast<const float4*>(&ws[c0o][kj]);
                acc0 = fmaf(a.x, w.x, acc0); acc0 = fmaf(a.y, w.y, acc0);
                acc0 = fmaf(a.z, w.z, acc0); acc0 = fmaf(a.w, w.w, acc0);
            }
            if (o1 < 440) {
                const float4 a = *reinterpret_cast<const float4*>(
                    &hs[r1o][chunk * 64 + kj]);
                const float4 w = *reinterpret_cast<const float4*>(&ws[c1o][kj]);
                acc1 = fmaf(a.x, w.x, acc1); acc1 = fmaf(a.y, w.y, acc1);
                acc1 = fmaf(a.z, w.z, acc1); acc1 = fmaf(a.w, w.w, acc1);
            }
        }
    }
    zs[r0o][c0o] = acc0 + b3[c0o];
    if (o1 < 440) zs[r1o][c1o] = acc1 + b3[c1o];
    __syncthreads();

    if (t < 48) {
        const int r     = t / 6;
        const int g     = t - 6 * r;
        const int start = (g == 0) ? 0 : 5 + 10 * (g - 1);
        const int len   = (g == 0) ? 5 : 10;
        float m = -3.0e38f;
        for (int c = 0; c < len; ++c) m = fmaxf(m, zs[r][start + c]);
        float s = 0.f;
        for (int c = 0; c < len; ++c) s += __expf(zs[r][start + c] - m);
        const float inv = 1.0f / s;
        float* dst = &g_x3[(size_t)(r0 + r) * 64];
        for (int c = 0; c < len; ++c)
            dst[start + c] = __expf(zs[r][start + c] - m) * inv;
    }
}

// ---------------------------------------------------------------------------
// Kernel B: expansion.  out[b, i] constant over runs of 10 (r = i/10).
// grid (8, 512), 640 threads; loop-invariant per-thread run phase;
// streaming (evict-first) float4 stores.
// ---------------------------------------------------------------------------
__global__ void __launch_bounds__(640) expand_kernel(float* __restrict__ out)
{
    __shared__ float p[64];
    __shared__ float sv[1288];

    const unsigned t   = threadIdx.x;
    const unsigned bx  = blockIdx.x;
    const unsigned b   = blockIdx.y;
    const unsigned pad = b & 3u;
    const unsigned rbase = bx * 1280u;   // multiple of 10

    if (t < 64u) p[t] = g_x3[(size_t)b * 64u + t];
    __syncthreads();

    #pragma unroll
    for (unsigned kk = 0; kk < 3u; ++kk) {
        const unsigned ri = t + kk * 640u;
        if (ri < 1282u) {
            const unsigned r = rbase + ri;
            float v = 0.f;
            if (r < 10000u) {
                if (r == 0u) {
                    v = p[0];
                } else if (r < 10u) {
                    v = p[1] * p[5 + r];
                } else if (r < 100u) {
                    const unsigned q1 = r / 10u;
                    v = p[2] * p[5 + q1] * p[15 + (r - 10u * q1)];
                } else if (r < 1000u) {
                    const unsigned q1 = r / 10u, q2 = r / 100u;
                    v = p[3] * p[5 + q2] * p[15 + (q1 - 10u * q2)]
                             * p[25 + (r - 10u * q1)];
                } else {
                    const unsigned q1 = r / 10u, q2 = r / 100u, q3 = r / 1000u;
                    v = p[4] * p[5 + q3] * p[15 + (q2 - 10u * q3)]
                             * p[25 + (q1 - 10u * q2)] * p[35 + (r - 10u * q1)];
                }
            }
            sv[ri] = v;
        }
    }
    __syncthreads();

    float* o = out + (size_t)b * 99999u;
    float4* ov = reinterpret_cast<float4*>(o + pad);   // 16B-aligned

    const unsigned ph  = pad + 4u * t;       // < 2560
    const unsigned rt  = ph / 10u;
    const unsigned rem = ph - 10u * rt;
    const bool c1 = (rem + 1u < 10u);
    const bool c2 = (rem + 2u < 10u);
    const bool c3 = (rem + 3u < 10u);

    if (bx < 7u) {
        unsigned vi = bx * 3200u + t;
        unsigned ri = rt;
        #pragma unroll
        for (int k = 0; k < 5; ++k) {
            const float f0 = sv[ri];
            const float f1 = sv[ri + 1u];
            float4 w;
            w.x = f0;
            w.y = c1 ? f0 : f1;
            w.z = c2 ? f0 : f1;
            w.w = c3 ? f0 : f1;
            __stcs(&ov[vi], w);
            vi += 640u;
            ri += 256u;
        }
        if (bx == 0u) {
            if (t == 0u) o[0] = p[1] * p[5];
            else if (t < pad) o[t] = p[0];   // pad <= 3
        }
    } else {
        unsigned vi = 22400u + t;
        unsigned ri = rt;
        #pragma unroll
        for (int k = 0; k < 5; ++k) {
            if (vi < 24999u) {
                const float f0 = sv[ri];
                const float f1 = sv[ri + 1u];
                float4 w;
                w.x = f0;
                w.y = c1 ? f0 : f1;
                w.z = c2 ? f0 : f1;
                w.w = c3 ? f0 : f1;
                __stcs(&ov[vi], w);
            }
            vi += 640u;
            ri += 256u;
        }
        if (t < 3u - pad) {
            o[pad + 99996u + t] = sv[1039];
        }
    }
}

// ---------------------------------------------------------------------------
extern "C" void kernel_launch(void* const* d_in, const int* in_sizes, int n_in,
                              void* d_out, int out_size)
{
    (void)in_sizes; (void)n_in; (void)out_size;
    const float* x  = (const float*)d_in[0];   // [512, 512]
    const float* w2 = (const float*)d_in[1];   // [256, 512]
    const float* b2 = (const float*)d_in[2];   // [256]
    const float* w3 = (const float*)d_in[3];   // [55, 256]
    const float* b3 = (const float*)d_in[4];   // [55]
    float* out = (float*)d_out;                // [512, 99999]

    gemm1_part_kernel<<<dim3(16, 4, 16), 128>>>(x, w2);
    head_kernel<<<64, 256>>>(b2, w3, b3);
    expand_kernel<<<dim3(8, 512), 640>>>(out);
}